// round 8
// baseline (speedup 1.0000x reference)
#include <cuda_runtime.h>

// DistanceTransformMap: exact EDT + sqrt via (A) bitmap compress, (B) fused
// row-distance-from-bits + column search.
//
// A: __ballot_sync packs zero-pixel bits (mask<=0.5) into 12 words/row.
// B: one block per (batch, 12-column strip). Loads the batch's whole bitmap
//    (18KB, contiguous+coalesced), computes row EDT for its 4608 (x,y) via
//    __ffs/__clz word scans (exact for all inputs; all-ones row -> LARGE),
//    then the proven column search:
//    - near window d<=4 unconditional (extra candidates are upper bounds);
//    - far case (best>25) clamped-index loop: clamped slots always land on
//      LARGE pads (left 0..7, right 392..399), LARGE + d^2 never wins.
// All intermediates are exact integers < 2^24 in fp32 -> bit-exact vs ref.

constexpr int Bn = 4;
constexpr int Hn = 384;
constexpr int Wn = 384;
constexpr int N  = 384;
constexpr int WPR = 12;                       // 32-bit words per row
constexpr float LARGE = 2.0f * (float)(Hn * Hn + Wn * Wn);  // 589824 > 383^2

constexpr int PAD = 8;
constexpr int LWD = N + 2 * PAD;              // 400 valid slots per line
constexpr int LWP = 403;                      // line stride (odd)
constexpr int NT2 = 768;

__device__ unsigned g_bm[Bn * Hn * WPR];      // zero-pixel bitmap

// ---------------- Kernel A: ballot compress ----------------
__global__ __launch_bounds__(384) void edt_compress(const float* __restrict__ mask) {
    const int w = threadIdx.x >> 5, lane = threadIdx.x & 31;
    const int L = blockIdx.x * 12 + w;        // row = b*Hn + y
    const size_t base = (size_t)L * N;
#pragma unroll
    for (int k = 0; k < 12; ++k) {
        const float v = mask[base + lane + 32 * k];       // coalesced
        const unsigned m = __ballot_sync(0xffffffffu, v <= 0.5f);
        if (lane == k) g_bm[L * WPR + k] = m;
    }
}

// ---------------- Kernel B ----------------
__device__ __forceinline__ float near_far(const float* __restrict__ row,
                                          float best, int i) {
    if (best > 25.0f) {                        // rare exact continuation
        float df = 5.0f;
        int d = 5;
        const int ip = i + PAD;
        while (df * df < best && d < N) {
#pragma unroll
            for (int u = 0; u < 4; ++u) {
                const int jr = min(ip + d + u, LWD - 1);
                const int jl = max(ip - d - u, 0);
                const float e = df + (float)u;
                best = fminf(best, fmaf(e, e, fminf(row[jr], row[jl])));
            }
            df += 4.0f;
            d += 4;
        }
    }
    return best;
}

__global__ __launch_bounds__(NT2, 1) void edt_main(float* __restrict__ out) {
    __shared__ __align__(16) unsigned sh_bm[Hn * 13];   // bitmap; later aliased as output stage
    __shared__ float lines[12 * LWP];                   // 12 padded column-lines
    float* const sh_o = reinterpret_cast<float*>(sh_bm);

    const int t = threadIdx.x;
    const int b = blockIdx.x >> 5;             // batch
    const int x0 = (blockIdx.x & 31) * 12;     // column strip

    // 1. Load batch bitmap: 4608 contiguous words, fully coalesced.
    const unsigned* __restrict__ src = g_bm + (size_t)b * Hn * WPR;
#pragma unroll
    for (int r = 0; r < 6; ++r) {
        const int idx = t + NT2 * r;
        const int y = idx / 12, j = idx - y * 12;
        sh_bm[y * 13 + j] = src[idx];
    }
    if (t < 12 * PAD) {                        // LARGE pads for column lines
        const int c = t >> 3, o = t & 7;
        lines[c * LWP + o] = LARGE;
        lines[c * LWP + LWD - PAD + o] = LARGE;
    }
    __syncthreads();

    // 2. Row distances for my strip: thread owns fixed y, 6 x-values.
    {
        const int w = t >> 5, lane = t & 31;
        const int yb = (w << 4) + (lane & 15);            // y in 0..383
        const int xoff = lane >> 4;                       // 0 or 1
        const unsigned* __restrict__ rowbm = &sh_bm[yb * 13];
#pragma unroll
        for (int k = 0; k < 6; ++k) {
            const int xl = xoff + 2 * k;                  // local x (0..11)
            const int xg = x0 + xl;
            const int jw = xg >> 5, bp = xg & 31;
            const unsigned wc = rowbm[jw];
            // right: nearest set bit at position >= xg
            int dr = 0x7fff;
            const unsigned wr = wc >> bp;
            if (wr) {
                dr = __ffs(wr) - 1;
            } else {
                for (int j = jw + 1; j < 12; ++j) {
                    const unsigned uu = rowbm[j];
                    if (uu) { dr = j * 32 - xg + __ffs(uu) - 1; break; }
                }
            }
            // left: nearest set bit at position <= xg
            int dl = 0x7fff;
            const unsigned wl = wc << (31 - bp);
            if (wl) {
                dl = __clz(wl);
            } else {
                for (int j = jw - 1; j >= 0; --j) {
                    const unsigned uu = rowbm[j];
                    if (uu) { dl = xg - j * 32 - 31 + __clz(uu); break; }
                }
            }
            const int d = min(dl, dr);
            float g = LARGE;
            if (d < 384) g = (float)(d * d);
            lines[xl * LWP + PAD + yb] = g;
        }
    }
    __syncthreads();                           // lines ready; sh_bm reads done

    // 3. Column search (proven R7 code): 2 warps per column-line.
    const int w = t >> 5, lane = t & 31;
    const int cl = (w < 12) ? w : (w - 12);
    const int half = (w < 12) ? 0 : 192;
    const float* __restrict__ row = &lines[cl * LWP];
    const int ibase = half + lane;

    float best[6];
#pragma unroll
    for (int gq = 0; gq < 6; gq += 3) {
        float a[3][9];
#pragma unroll
        for (int s = 0; s < 3; ++s) {
            const float* p = row + PAD + ibase + 32 * (gq + s);
            a[s][0] = p[0];
            a[s][1] = p[1];  a[s][2] = p[-1];
            a[s][3] = p[2];  a[s][4] = p[-2];
            a[s][5] = p[3];  a[s][6] = p[-3];
            a[s][7] = p[4];  a[s][8] = p[-4];
        }
#pragma unroll
        for (int s = 0; s < 3; ++s) {
            const float c1 = fminf(a[s][1], a[s][2]) + 1.0f;
            const float c2 = fminf(a[s][3], a[s][4]) + 4.0f;
            const float c3 = fminf(a[s][5], a[s][6]) + 9.0f;
            const float c4 = fminf(a[s][7], a[s][8]) + 16.0f;
            best[gq + s] = fminf(a[s][0], fminf(fminf(c1, c2), fminf(c3, c4)));
        }
    }
#pragma unroll
    for (int s = 0; s < 6; ++s)
        best[s] = near_far(row, best[s], ibase + 32 * s);

    // 4. Stage + coalesced-ish tile store (sh_o aliases sh_bm; safe: all
    //    bitmap reads completed before the previous __syncthreads).
#pragma unroll
    for (int s = 0; s < 6; ++s)
        sh_o[(ibase + 32 * s) * 13 + cl] = sqrtf(best[s]);
    __syncthreads();

    const int c_ld = t % 12, y_ld = t / 12;
    float* __restrict__ dst = out + ((size_t)b * Hn) * Wn + x0 + c_ld;
#pragma unroll
    for (int r = 0; r < 6; ++r) {
        const int y = y_ld + 64 * r;
        dst[(size_t)y * Wn] = sh_o[y * 13 + c_ld];
    }
}

extern "C" void kernel_launch(void* const* d_in, const int* in_sizes, int n_in,
                              void* d_out, int out_size) {
    const float* mask = (const float*)d_in[0];
    float* out = (float*)d_out;
    (void)in_sizes; (void)n_in; (void)out_size;

    edt_compress<<<Bn * Hn / 12, 384>>>(mask);
    edt_main<<<Bn * (Wn / 12), NT2>>>(out);
}

// round 9
// speedup vs baseline: 1.0239x; 1.0239x over previous
#include <cuda_runtime.h>

// DistanceTransformMap: exact EDT + sqrt.
// A) ballot-compress zero-pixel bitmap (12 words/row).
// B) per-(batch, 4-column strip) block: load batch bitmap (18KB coalesced),
//    row distances via 64-bit funnel bit-scans, then column expanding search.
//
// Exactness:
//  - funnel covers >=33 bits each direction; empty window -> exact word loop;
//    zero-padded word slots at j=-1,12,13 make boundaries exact; no zero in
//    row -> d>=384 -> LARGE (reference min attained at j=i gives LARGE too).
//  - column near window d<=4 unconditional: extra candidates are upper bounds.
//  - far case (best>25): clamped indices always land on LARGE pads
//    (left 0..7, right 392..399); LARGE + d^2 > LARGE >= best0 never wins.
// All intermediates are exact integers < 2^24 in fp32 -> bit-exact vs ref.

constexpr int Bn = 4;
constexpr int Hn = 384;
constexpr int Wn = 384;
constexpr int N  = 384;
constexpr int WPR = 12;                       // bitmap words per row
constexpr float LARGE = 2.0f * (float)(Hn * Hn + Wn * Wn);  // 589824 > 383^2

constexpr int PAD = 8;
constexpr int LWD = N + 2 * PAD;              // 400
constexpr int LWP = 403;                      // padded line stride (odd)
constexpr int CPB = 4;                        // columns per block
constexpr int NT  = 384;
constexpr int BMS = 15;                       // bitmap row stride (odd)

__device__ unsigned g_bm[Bn * Hn * WPR];

// ---------------- Kernel A: ballot compress ----------------
__global__ __launch_bounds__(384) void edt_compress(const float* __restrict__ mask) {
    const int w = threadIdx.x >> 5, lane = threadIdx.x & 31;
    const int L = blockIdx.x * 12 + w;
    const size_t base = (size_t)L * N;
#pragma unroll
    for (int k = 0; k < 12; ++k) {
        const float v = mask[base + lane + 32 * k];
        const unsigned m = __ballot_sync(0xffffffffu, v <= 0.5f);
        if (lane == k) g_bm[L * WPR + k] = m;
    }
}

// ---------------- Kernel B ----------------
__device__ __forceinline__ float near_far(const float* __restrict__ row,
                                          float best, int i) {
    if (best > 25.0f) {
        float df = 5.0f;
        int d = 5;
        const int ip = i + PAD;
        while (df * df < best && d < N) {
#pragma unroll
            for (int u = 0; u < 4; ++u) {
                const int jr = min(ip + d + u, LWD - 1);
                const int jl = max(ip - d - u, 0);
                const float e = df + (float)u;
                best = fminf(best, fmaf(e, e, fminf(row[jr], row[jl])));
            }
            df += 4.0f;
            d += 4;
        }
    }
    return best;
}

__global__ __launch_bounds__(NT, 3) void edt_main(float* __restrict__ out) {
    __shared__ __align__(16) unsigned sh_bm[Hn * BMS];  // bitmap rows (padded), later output stage
    __shared__ float lines[CPB * LWP];
    float* const sh_o = reinterpret_cast<float*>(sh_bm);

    const int t = threadIdx.x;
    const int b = blockIdx.x / (Wn / CPB);
    const int x0 = (blockIdx.x - b * (Wn / CPB)) * CPB;

    // 1. Load batch bitmap (4608 contiguous words) + zero word-pads + LARGE pads.
    const unsigned* __restrict__ src = g_bm + (size_t)b * Hn * WPR;
#pragma unroll
    for (int r = 0; r < 12; ++r) {
        const int idx = t + NT * r;
        const int y = idx / 12, j = idx - y * 12;
        sh_bm[y * BMS + 1 + j] = src[idx];
    }
    // zero slots 0 (j=-1), 13 (j=12), 14 (j=13) per row
    {
        const int y = t;
        sh_bm[y * BMS + 0] = 0u;
        sh_bm[y * BMS + 13] = 0u;
        sh_bm[y * BMS + 14] = 0u;
    }
    if (t < CPB * PAD) {
        const int c = t >> 3, o = t & 7;
        lines[c * LWP + o] = LARGE;
        lines[c * LWP + LWD - PAD + o] = LARGE;
    }
    __syncthreads();

    // 2. Row distances: thread t owns y=t, computes CPB columns via funnels.
    {
        const int y = t;
        const unsigned* __restrict__ rowbm = &sh_bm[y * BMS + 1];
        const int jw = x0 >> 5;               // x0 % 4 == 0 -> bp0 <= 28
        const unsigned wm1 = rowbm[jw - 1];
        const unsigned w0  = rowbm[jw];
        const unsigned wp1 = rowbm[jw + 1];
        const unsigned long long vr = ((unsigned long long)wp1 << 32) | w0;
        const unsigned long long vl = ((unsigned long long)w0 << 32) | wm1;
        const int bp0 = x0 & 31;
#pragma unroll
        for (int xl = 0; xl < CPB; ++xl) {
            const int bp = bp0 + xl;          // <= 31 always
            const int xg = x0 + xl;
            int dr, dl;
            const unsigned long long r64 = vr >> bp;
            if (r64) {
                dr = __ffsll(r64) - 1;
            } else {                           // exact fallback
                dr = 0x7fff;
                for (int j = jw + 2; j < 12; ++j) {
                    const unsigned uu = rowbm[j];
                    if (uu) { dr = j * 32 - xg + __ffs(uu) - 1; break; }
                }
            }
            const unsigned long long l64 = vl << (31 - bp);
            if (l64) {
                dl = __clzll(l64);
            } else {
                dl = 0x7fff;
                for (int j = jw - 2; j >= 0; --j) {
                    const unsigned uu = rowbm[j];
                    if (uu) { dl = xg - j * 32 - 31 + __clz(uu); break; }
                }
            }
            const int d = min(dl, dr);
            lines[xl * LWP + PAD + y] = (d < 384) ? (float)(d * d) : LARGE;
        }
    }
    __syncthreads();

    // 3. Column search: 12 warps = 3 segments x 4 columns, 4 searches/thread.
    const int w = t >> 5, lane = t & 31;
    const int cl = w & 3, seg = w >> 2;
    const float* __restrict__ row = &lines[cl * LWP];
    const int ibase = seg * 128 + lane;

    float best[4];
#pragma unroll
    for (int gq = 0; gq < 4; gq += 2) {       // groups of 2 searches
        float a[2][9];
#pragma unroll
        for (int s = 0; s < 2; ++s) {
            const float* p = row + PAD + ibase + 32 * (gq + s);
            a[s][0] = p[0];
            a[s][1] = p[1];  a[s][2] = p[-1];
            a[s][3] = p[2];  a[s][4] = p[-2];
            a[s][5] = p[3];  a[s][6] = p[-3];
            a[s][7] = p[4];  a[s][8] = p[-4];
        }
#pragma unroll
        for (int s = 0; s < 2; ++s) {
            const float c1 = fminf(a[s][1], a[s][2]) + 1.0f;
            const float c2 = fminf(a[s][3], a[s][4]) + 4.0f;
            const float c3 = fminf(a[s][5], a[s][6]) + 9.0f;
            const float c4 = fminf(a[s][7], a[s][8]) + 16.0f;
            best[gq + s] = fminf(a[s][0], fminf(fminf(c1, c2), fminf(c3, c4)));
        }
    }
#pragma unroll
    for (int s = 0; s < 4; ++s)
        best[s] = near_far(row, best[s], ibase + 32 * s);

    __syncthreads();                          // sh_bm reads done -> alias safe
#pragma unroll
    for (int s = 0; s < 4; ++s)
        sh_o[(ibase + 32 * s) * BMS + cl] = sqrtf(best[s]);
    __syncthreads();

    // 4. Tile store: 1536 floats, 4 per y.
    const int c_st = t & 3, y_st = t >> 2;
    float* __restrict__ dst = out + ((size_t)b * Hn) * Wn + x0 + c_st;
#pragma unroll
    for (int r = 0; r < 4; ++r) {
        const int y = y_st + 96 * r;
        dst[(size_t)y * Wn] = sh_o[y * BMS + c_st];
    }
}

extern "C" void kernel_launch(void* const* d_in, const int* in_sizes, int n_in,
                              void* d_out, int out_size) {
    const float* mask = (const float*)d_in[0];
    float* out = (float*)d_out;
    (void)in_sizes; (void)n_in; (void)out_size;

    edt_compress<<<Bn * Hn / 12, 384>>>(mask);
    edt_main<<<Bn * (Wn / CPB), NT>>>(out);
}